// round 1
// baseline (speedup 1.0000x reference)
#include <cuda_runtime.h>
#include <math.h>
#include <stdint.h>

#define E_TOTAL 500000
#define CDIM 128

// Scratch (static device allocations are allowed; runtime allocs are not)
__device__ float g_W1[256 * 128];   // fused weights for attention-u path
__device__ float g_W2[256 * 256];   // fused weights for edge-MLP path
__device__ float g_c1[128];         // fused bias for u
__device__ float g_c2[256];         // fused bias for v (pre-attn part)
__device__ float g_attn[E_TOTAL];   // per-edge sigmoid gate
__device__ int   g_idx64;           // 1 if edge_index is int64, 0 if int32

// ---------------------------------------------------------------------------
// Detect edge_index dtype: if int64 (little-endian, values < 2^31), every odd
// 32-bit word of the first 256 entries is zero. For int32 those words are
// real random indices (P(all zero) ~ 0).
// ---------------------------------------------------------------------------
__global__ void detect_idx_kernel(const int* __restrict__ idx32) {
    if (threadIdx.x == 0) {
        int nz = 0;
        for (int i = 0; i < 256; i++) nz |= idx32[2 * i + 1];
        g_idx64 = (nz == 0) ? 1 : 0;
    }
}

// ---------------------------------------------------------------------------
// Precompute fused weights:
//   W1[k][j] = (k<128 ? Ws[k][:] : Wt[k-128][:]) . Wa1[(k<128?0:128)+m][j]
//   W2[k][j] = (k<128 ? Ws[k][:] : Wt[k-128][:]) . We [(k<128?0:128)+m][j]
// ---------------------------------------------------------------------------
__global__ void precompute_W_kernel(const float* __restrict__ Ws, const float* __restrict__ Wt,
                                    const float* __restrict__ Wa1, const float* __restrict__ We) {
    int t = blockIdx.x * blockDim.x + threadIdx.x;
    if (t >= 256 * 384) return;
    int k = t / 384;
    int j = t % 384;
    const float* arow = (k < 128) ? (Ws + k * 128) : (Wt + (k - 128) * 128);
    float sum = 0.f;
    if (j < 128) {
        const float* bcol = Wa1 + ((k < 128) ? 0 : 128) * 128 + j;
        #pragma unroll 4
        for (int m = 0; m < 128; m++) sum = fmaf(arow[m], bcol[m * 128], sum);
        g_W1[k * 128 + j] = sum;
    } else {
        int jj = j - 128;
        const float* bcol = We + ((k < 128) ? 0 : 128) * 256 + jj;
        #pragma unroll 4
        for (int m = 0; m < 128; m++) sum = fmaf(arow[m], bcol[m * 256], sum);
        g_W2[k * 256 + jj] = sum;
    }
}

__global__ void precompute_c_kernel(const float* __restrict__ Wa1, const float* __restrict__ We,
                                    const float* __restrict__ bs, const float* __restrict__ bt,
                                    const float* __restrict__ ba1) {
    int j = blockIdx.x * blockDim.x + threadIdx.x;
    if (j < 128) {
        float s = ba1[j];
        for (int m = 0; m < 128; m++)
            s += bs[m] * Wa1[m * 128 + j] + bt[m] * Wa1[(128 + m) * 128 + j];
        g_c1[j] = s;
    } else if (j < 384) {
        int jj = j - 128;
        float s = 0.f;
        for (int m = 0; m < 128; m++)
            s += bs[m] * We[m * 256 + jj] + bt[m] * We[(128 + m) * 256 + jj];
        g_c2[jj] = s;
    }
}

// ---------------------------------------------------------------------------
// Kernel 1: attn[e] = sigmoid( relu(X[e] @ W1 + c1) . Wa2 + ba2 )
// Tile: 128 edges x 128 cols, K=256. W1 fully resident in smem (128 KB).
// 256 threads = 16 rowg x 16 colg, each 8x8 micro-tile, cols strided by 16
// (bank-conflict-free scalar B reads).
// ---------------------------------------------------------------------------
#define TM1 128
#define NT1 3907
#define SMEM1 165888

__global__ void __launch_bounds__(256, 1) attn_kernel(
    const float* __restrict__ emb, const void* __restrict__ eidx,
    const float* __restrict__ Wa2, const float* __restrict__ ba2)
{
    extern __shared__ float sm[];
    float* sW1  = sm;                    // 256*128
    float* sA   = sW1 + 256 * 128;       // 64*128 (k-major: sA[k][row])
    float* sC1  = sA + 64 * 128;         // 128
    float* sWa2 = sC1 + 128;             // 128
    int*   sSrc = (int*)(sWa2 + 128);    // 128
    int*   sTgt = sSrc + 128;            // 128

    const int tid = threadIdx.x;
    for (int i = tid; i < 8192; i += 256)
        ((float4*)sW1)[i] = ((const float4*)g_W1)[i];
    if (tid < 128) { sC1[tid] = g_c1[tid]; sWa2[tid] = Wa2[tid]; }
    const int rowg = tid >> 4;
    const int colg = tid & 15;
    const bool is64 = (g_idx64 != 0);
    const float ba2v = ba2[0];

    for (int tile = blockIdx.x; tile < NT1; tile += gridDim.x) {
        const int e0 = tile * TM1;
        const int cnt = min(TM1, E_TOTAL - e0);
        if (tid < TM1) {
            int s = 0, t = 0;
            if (tid < cnt) {
                if (is64) {
                    const long long* p = (const long long*)eidx;
                    s = (int)p[e0 + tid]; t = (int)p[E_TOTAL + e0 + tid];
                } else {
                    const int* p = (const int*)eidx;
                    s = p[e0 + tid]; t = p[E_TOTAL + e0 + tid];
                }
            }
            sSrc[tid] = s; sTgt[tid] = t;
        }

        float acc[8][8];
        #pragma unroll
        for (int i = 0; i < 8; i++) {
            #pragma unroll
            for (int j = 0; j < 8; j++) acc[i][j] = 0.f;
        }

        #pragma unroll 1
        for (int kc = 0; kc < 4; kc++) {
            __syncthreads();
            {   // gather A chunk: rows=edges, 64 k-values from src (kc<2) or tgt node
                const int r = tid >> 1, h = tid & 1;
                const int node = (kc < 2) ? sSrc[r] : sTgt[r];
                const float4* src = (const float4*)(emb + (size_t)node * CDIM + (kc & 1) * 64 + h * 32);
                const bool valid = (r < cnt);
                #pragma unroll
                for (int q = 0; q < 8; q++) {
                    float4 v = valid ? src[q] : make_float4(0.f, 0.f, 0.f, 0.f);
                    const int kk = h * 32 + q * 4;
                    sA[(kk + 0) * TM1 + r] = v.x;
                    sA[(kk + 1) * TM1 + r] = v.y;
                    sA[(kk + 2) * TM1 + r] = v.z;
                    sA[(kk + 3) * TM1 + r] = v.w;
                }
            }
            __syncthreads();
            const float* wb = sW1 + kc * 64 * 128;
            #pragma unroll 8
            for (int kk = 0; kk < 64; kk++) {
                float4 a0 = *(const float4*)(sA + kk * TM1 + rowg * 8);
                float4 a1 = *(const float4*)(sA + kk * TM1 + rowg * 8 + 4);
                float a[8] = {a0.x, a0.y, a0.z, a0.w, a1.x, a1.y, a1.z, a1.w};
                float b[8];
                #pragma unroll
                for (int j = 0; j < 8; j++) b[j] = wb[kk * 128 + colg + 16 * j];
                #pragma unroll
                for (int i = 0; i < 8; i++) {
                    #pragma unroll
                    for (int j = 0; j < 8; j++)
                        acc[i][j] = fmaf(a[i], b[j], acc[i][j]);
                }
            }
        }

        // epilogue: relu(u) . Wa2, reduce across 16 colg lanes, sigmoid
        float part[8];
        #pragma unroll
        for (int i = 0; i < 8; i++) {
            float p = 0.f;
            #pragma unroll
            for (int j = 0; j < 8; j++) {
                const int col = colg + 16 * j;
                float u = acc[i][j] + sC1[col];
                u = fmaxf(u, 0.f);
                p = fmaf(u, sWa2[col], p);
            }
            part[i] = p;
        }
        #pragma unroll
        for (int i = 0; i < 8; i++) {
            #pragma unroll
            for (int o = 8; o >= 1; o >>= 1)
                part[i] += __shfl_xor_sync(0xffffffffu, part[i], o);
        }
        if (colg == 0) {
            #pragma unroll
            for (int i = 0; i < 8; i++) {
                const int r = rowg * 8 + i;
                if (r < cnt) {
                    const float x = part[i] + ba2v;
                    g_attn[e0 + r] = 1.f / (1.f + expf(-x));
                }
            }
        }
    }
}

// ---------------------------------------------------------------------------
// Kernel 2: v = X @ W2 + c2 ; z = attn*v + be ; GeGLU ; LayerNorm ; store.
// Tile: 128 edges x 256 cols, K=256. W2 streamed from L2 in 64-row chunks.
// 512 threads = 16 rowg x 32 colg, 8x8 micro-tile, cols strided by 32 so
// thread j-slot 0..3 holds x-part col c and j-slot 4..7 holds gate col c+128.
// LayerNorm = full-warp shfl reduction (warp == one rowg).
// ---------------------------------------------------------------------------
#define TM2 128
#define NT2 3907
#define SMEM2 102400

__global__ void __launch_bounds__(512, 1) edge_kernel(
    const float* __restrict__ emb, const void* __restrict__ eidx,
    const float* __restrict__ be, const float* __restrict__ gamma,
    const float* __restrict__ beta, float* __restrict__ out)
{
    extern __shared__ float sm[];
    float* sB  = sm;                 // 64*256
    float* sA  = sB + 64 * 256;      // 64*128
    float* sC2 = sA + 64 * 128;      // 256
    float* sBe = sC2 + 256;          // 256
    float* sGa = sBe + 256;          // 128
    float* sBt = sGa + 128;          // 128
    int*   sSrc = (int*)(sBt + 128); // 128
    int*   sTgt = sSrc + 128;        // 128

    const int tid = threadIdx.x;
    const int e0 = blockIdx.x * TM2;
    const int cnt = min(TM2, E_TOTAL - e0);

    if (tid < 256) { sC2[tid] = g_c2[tid]; sBe[tid] = be[tid]; }
    else if (tid < 384) { const int c = tid - 256; sGa[c] = gamma[c]; sBt[c] = beta[c]; }
    if (tid < TM2) {
        int s = 0, t = 0;
        if (tid < cnt) {
            if (g_idx64) {
                const long long* p = (const long long*)eidx;
                s = (int)p[e0 + tid]; t = (int)p[E_TOTAL + e0 + tid];
            } else {
                const int* p = (const int*)eidx;
                s = p[e0 + tid]; t = p[E_TOTAL + e0 + tid];
            }
        }
        sSrc[tid] = s; sTgt[tid] = t;
    }

    const int rowg = tid >> 5;
    const int colg = tid & 31;

    float acc[8][8];
    #pragma unroll
    for (int i = 0; i < 8; i++) {
        #pragma unroll
        for (int j = 0; j < 8; j++) acc[i][j] = 0.f;
    }

    #pragma unroll 1
    for (int kc = 0; kc < 4; kc++) {
        __syncthreads();
        {   // stream W2 chunk (contiguous, fully coalesced, L2-resident)
            const float4* gB = (const float4*)(g_W2 + kc * 64 * 256);
            float4* s4 = (float4*)sB;
            #pragma unroll
            for (int q = 0; q < 8; q++) s4[tid + q * 512] = gB[tid + q * 512];
        }
        {   // gather A chunk
            const int r = tid >> 2, qt = tid & 3;
            const int node = (kc < 2) ? sSrc[r] : sTgt[r];
            const float4* src = (const float4*)(emb + (size_t)node * CDIM + (kc & 1) * 64 + qt * 16);
            const bool valid = (r < cnt);
            #pragma unroll
            for (int q = 0; q < 4; q++) {
                float4 v = valid ? src[q] : make_float4(0.f, 0.f, 0.f, 0.f);
                const int kk = qt * 16 + q * 4;
                sA[(kk + 0) * TM2 + r] = v.x;
                sA[(kk + 1) * TM2 + r] = v.y;
                sA[(kk + 2) * TM2 + r] = v.z;
                sA[(kk + 3) * TM2 + r] = v.w;
            }
        }
        __syncthreads();
        #pragma unroll 8
        for (int kk = 0; kk < 64; kk++) {
            float4 a0 = *(const float4*)(sA + kk * TM2 + rowg * 8);
            float4 a1 = *(const float4*)(sA + kk * TM2 + rowg * 8 + 4);
            float a[8] = {a0.x, a0.y, a0.z, a0.w, a1.x, a1.y, a1.z, a1.w};
            float b[8];
            #pragma unroll
            for (int j = 0; j < 8; j++) b[j] = sB[kk * 256 + colg + 32 * j];
            #pragma unroll
            for (int i = 0; i < 8; i++) {
                #pragma unroll
                for (int j = 0; j < 8; j++)
                    acc[i][j] = fmaf(a[i], b[j], acc[i][j]);
            }
        }
    }

    // epilogue: z = attn*(v + c2) + be ; g = z_x * gelu(z_gate) ; LayerNorm
    #pragma unroll
    for (int i = 0; i < 8; i++) {
        const int r = rowg * 8 + i;
        const float att = (r < cnt) ? g_attn[e0 + r] : 0.f;
        float gv[4];
        #pragma unroll
        for (int j = 0; j < 4; j++) {
            const int col = colg + 32 * j;
            const float zx = fmaf(att, acc[i][j]     + sC2[col],       sBe[col]);
            const float zg = fmaf(att, acc[i][j + 4] + sC2[col + 128], sBe[col + 128]);
            const float gel = 0.5f * zg * (1.f + erff(zg * 0.70710678118654752f));
            gv[j] = zx * gel;
        }
        float s1 = gv[0] + gv[1] + gv[2] + gv[3];
        float s2 = gv[0] * gv[0] + gv[1] * gv[1] + gv[2] * gv[2] + gv[3] * gv[3];
        #pragma unroll
        for (int o = 16; o >= 1; o >>= 1) {
            s1 += __shfl_xor_sync(0xffffffffu, s1, o);
            s2 += __shfl_xor_sync(0xffffffffu, s2, o);
        }
        const float mu = s1 * (1.f / 128.f);
        const float var = s2 * (1.f / 128.f) - mu * mu;
        const float rstd = rsqrtf(var + 1e-5f);
        if (r < cnt) {
            #pragma unroll
            for (int j = 0; j < 4; j++) {
                const int col = colg + 32 * j;
                out[(size_t)(e0 + r) * CDIM + col] = (gv[j] - mu) * rstd * sGa[col] + sBt[col];
            }
        }
    }
}

// ---------------------------------------------------------------------------
extern "C" void kernel_launch(void* const* d_in, const int* in_sizes, int n_in,
                              void* d_out, int out_size) {
    const float* emb   = (const float*)d_in[0];
    const void*  eidx  = d_in[1];
    const float* Ws    = (const float*)d_in[2];
    const float* bs    = (const float*)d_in[3];
    const float* Wt    = (const float*)d_in[4];
    const float* bt    = (const float*)d_in[5];
    const float* Wa1   = (const float*)d_in[6];
    const float* ba1   = (const float*)d_in[7];
    const float* Wa2   = (const float*)d_in[8];
    const float* ba2   = (const float*)d_in[9];
    const float* We    = (const float*)d_in[10];
    const float* be    = (const float*)d_in[11];
    const float* gamma = (const float*)d_in[12];
    const float* beta  = (const float*)d_in[13];
    float* out = (float*)d_out;

    cudaFuncSetAttribute(attn_kernel, cudaFuncAttributeMaxDynamicSharedMemorySize, SMEM1);
    cudaFuncSetAttribute(edge_kernel, cudaFuncAttributeMaxDynamicSharedMemorySize, SMEM2);

    detect_idx_kernel<<<1, 32>>>((const int*)eidx);
    precompute_W_kernel<<<(256 * 384 + 255) / 256, 256>>>(Ws, Wt, Wa1, We);
    precompute_c_kernel<<<2, 256>>>(Wa1, We, bs, bt, ba1);
    attn_kernel<<<592, 256, SMEM1>>>(emb, eidx, Wa2, ba2);
    edge_kernel<<<NT2, 512, SMEM2>>>(emb, eidx, be, gamma, beta, out);
}